// round 5
// baseline (speedup 1.0000x reference)
#include <cuda_runtime.h>
#include <cuda_bf16.h>

#define BB 256
#define TT 2000
#define II 23
#define HH 128
#define G3 384
#define NTH 768          // recurrence threads: (row, k-half) pairs
#define TCH 100
#define NCH (TT / TCH)

// Scratch: gx[t][b][r] = W_ih[r,:].x[b,t,:] + b_ih[r]
__device__ float g_gx[(size_t)TT * BB * G3];

// ---- packed f32x2 helpers ----
__device__ __forceinline__ unsigned long long fma2(unsigned long long a,
                                                   unsigned long long b,
                                                   unsigned long long c) {
    unsigned long long d;
    asm("fma.rn.f32x2 %0, %1, %2, %3;" : "=l"(d) : "l"(a), "l"(b), "l"(c));
    return d;
}
__device__ __forceinline__ unsigned long long add2(unsigned long long a,
                                                   unsigned long long b) {
    unsigned long long d;
    asm("add.rn.f32x2 %0, %1, %2;" : "=l"(d) : "l"(a), "l"(b));
    return d;
}
__device__ __forceinline__ unsigned long long pack2(float lo, float hi) {
    unsigned long long d;
    asm("mov.b64 %0, {%1, %2};" : "=l"(d) : "f"(lo), "f"(hi));
    return d;
}
__device__ __forceinline__ void unpack2(unsigned long long v, float& lo, float& hi) {
    asm("mov.b64 {%0, %1}, %2;" : "=f"(lo), "=f"(hi) : "l"(v));
}
__device__ __forceinline__ float tanh_ap(float x) {
    float y;
    asm("tanh.approx.f32 %0, %1;" : "=f"(y) : "f"(x));
    return y;
}
__device__ __forceinline__ float sigmoid_ap(float x) {
    return fmaf(tanh_ap(0.5f * x), 0.5f, 0.5f);
}

// ============================================================
// Phase 1: gx[t][b][r]. grid (NCH, BB), block 384. (unchanged)
// ============================================================
__global__ __launch_bounds__(G3) void gx_kernel(
    const float* __restrict__ x,
    const float* __restrict__ Wih,
    const float* __restrict__ bih)
{
    const int b   = blockIdx.y;
    const int t0g = blockIdx.x * TCH;
    const int r   = threadIdx.x;

    __shared__ __align__(16) float xt[II][TCH + 8];

    const float* xbase = x + ((size_t)b * TT + t0g) * II;
    for (int e = r; e < TCH * II; e += G3) {
        int t = e / II;
        int k = e - t * II;
        xt[k][t] = xbase[e];
    }

    unsigned long long ww[II];
#pragma unroll
    for (int k = 0; k < II; k++) {
        float wv = Wih[r * II + k];
        ww[k] = pack2(wv, wv);
    }
    const float bv = bih[r];
    const unsigned long long bp = pack2(bv, bv);

    __syncthreads();

    for (int t0 = 0; t0 < TCH; t0 += 4) {
        unsigned long long a01 = bp, a23 = bp;
#pragma unroll
        for (int k = 0; k < II; k++) {
            ulonglong2 xv = *reinterpret_cast<const ulonglong2*>(&xt[k][t0]);
            a01 = fma2(ww[k], xv.x, a01);
            a23 = fma2(ww[k], xv.y, a23);
        }
        float g0, g1, g2, g3;
        unpack2(a01, g0, g1);
        unpack2(a23, g2, g3);
        size_t o = ((size_t)(t0g + t0) * BB + b) * G3 + r;
        const size_t stp = (size_t)BB * G3;
        g_gx[o]           = g0;
        g_gx[o + stp]     = g1;
        g_gx[o + 2 * stp] = g2;
        g_gx[o + 3 * stp] = g3;
    }
}

// ============================================================
// Phase 2: recurrence, k-split. grid 128, block 768, 2 batches/CTA.
// tid = 2*row + half. Thread owns W_hh[row, half*64 : half*64+64].
// Pair combine via shfl_xor(1). Gate rows: r in [0,128) reset,
// [128,256) update, [256,384) candidate.
// ============================================================
__global__ __launch_bounds__(NTH, 1) void gru_rec(
    const float* __restrict__ Whh,   // [3H, H]
    const float* __restrict__ bhh,   // [3H]
    float* __restrict__ out)         // [B, H]
{
    const int b0   = blockIdx.x * 2;
    const int tid  = threadIdx.x;
    const int row  = tid >> 1;
    const int half = tid & 1;

    __shared__ __align__(16) float h_sh[2][HH];
    __shared__ __align__(8) float2 rg2[HH];
    __shared__ __align__(8) float2 zg2[HH];
    __shared__ __align__(8) float2 gxn2[HH];
    __shared__ __align__(8) float2 ghn2[HH];

    // W_hh[row, half-k] packed f32x2: 32 u64
    unsigned long long wp[HH / 4];
    {
        const float4* src = reinterpret_cast<const float4*>(Whh + row * HH + half * (HH / 2));
#pragma unroll
        for (int j = 0; j < HH / 8; j++) {
            float4 v = src[j];
            wp[2 * j]     = pack2(v.x, v.y);
            wp[2 * j + 1] = pack2(v.z, v.w);
        }
    }
    const float my_bhh = bhh[row];

    if (tid < HH) { h_sh[0][tid] = 0.0f; h_sh[1][tid] = 0.0f; }

    // gx loaded by even lanes only (one per row)
    const float* gxp = g_gx + (size_t)b0 * G3 + row;   // + t*BB*G3 (+G3 for b1)
    const size_t stp = (size_t)BB * G3;

    float gx0 = 0.0f, gx1 = 0.0f;
    if (half == 0) { gx0 = gxp[0]; gx1 = gxp[G3]; }
    float hsum = 0.0f;
    __syncthreads();

    const int koff = half * (HH / 8);   // ulonglong2 index offset into h (16 f32 per 2 u64x2)

    for (int t = 0; t < TT; t++) {
        // prefetch next gx (even lanes)
        float gx0n = 0.0f, gx1n = 0.0f;
        if (half == 0 && (t + 1) < TT) {
            const float* p = gxp + (size_t)(t + 1) * stp;
            gx0n = p[0];
            gx1n = p[G3];
        }

        const ulonglong2* h0p = reinterpret_cast<const ulonglong2*>(h_sh[0]) + koff;
        const ulonglong2* h1p = reinterpret_cast<const ulonglong2*>(h_sh[1]) + koff;

        // ---- batch 0 half-dot (2 chains) ----
        unsigned long long a0 = 0ull, a1 = 0ull;
#pragma unroll
        for (int j = 0; j < HH / 8; j++) {
            ulonglong2 hv = h0p[j];
            a0 = fma2(wp[2 * j],     hv.x, a0);
            a1 = fma2(wp[2 * j + 1], hv.y, a1);
        }
        float p0lo, p0hi;
        unpack2(add2(a0, a1), p0lo, p0hi);
        float part0 = p0lo + p0hi;

        // ---- batch 1 half-dot ----
        a0 = 0ull; a1 = 0ull;
#pragma unroll
        for (int j = 0; j < HH / 8; j++) {
            ulonglong2 hv = h1p[j];
            a0 = fma2(wp[2 * j],     hv.x, a0);
            a1 = fma2(wp[2 * j + 1], hv.y, a1);
        }
        float p1lo, p1hi;
        unpack2(add2(a0, a1), p1lo, p1hi);
        float part1 = p1lo + p1hi;

        // pair combine: even lane ends with the full dot
        part0 += __shfl_xor_sync(0xffffffffu, part0, 1);
        part1 += __shfl_xor_sync(0xffffffffu, part1, 1);

        if (half == 0) {
            float gh0 = part0 + my_bhh;
            float gh1 = part1 + my_bhh;
            if (row < HH) {
                rg2[row] = make_float2(sigmoid_ap(gx0 + gh0), sigmoid_ap(gx1 + gh1));
            } else if (row < 2 * HH) {
                zg2[row - HH] = make_float2(sigmoid_ap(gx0 + gh0), sigmoid_ap(gx1 + gh1));
            } else {
                gxn2[row - 2 * HH] = make_float2(gx0, gx1);
                ghn2[row - 2 * HH] = make_float2(gh0, gh1);
            }
        }
        __syncthreads();

        // phase 2: h update. tid 0..255: batch = tid&1, elem = tid>>1
        if (tid < 2 * HH) {
            const int e = row;        // tid>>1
            const int bsel = half;    // tid&1
            float rv, zv, gxv, ghv, hold;
            if (bsel == 0) {
                rv = rg2[e].x; zv = zg2[e].x; gxv = gxn2[e].x; ghv = ghn2[e].x;
                hold = h_sh[0][e];
            } else {
                rv = rg2[e].y; zv = zg2[e].y; gxv = gxn2[e].y; ghv = ghn2[e].y;
                hold = h_sh[1][e];
            }
            float n  = tanh_ap(fmaf(rv, ghv, gxv));
            float hn = fmaf(zv, hold - n, n);
            h_sh[bsel][e] = hn;
            hsum += hn;
        }
        __syncthreads();

        gx0 = gx0n;
        gx1 = gx1n;
    }

    if (tid < 2 * HH) {
        const int e = row;
        const int bsel = half;
        out[(b0 + bsel) * HH + e] = hsum * (1.0f / (float)TT);
    }
}

extern "C" void kernel_launch(void* const* d_in, const int* in_sizes, int n_in,
                              void* d_out, int out_size) {
    const float* x   = (const float*)d_in[0];
    const float* Wih = (const float*)d_in[1];
    const float* Whh = (const float*)d_in[2];
    const float* bih = (const float*)d_in[3];
    const float* bhh = (const float*)d_in[4];
    float* out = (float*)d_out;
    (void)in_sizes; (void)n_in; (void)out_size;

    gx_kernel<<<dim3(NCH, BB), G3>>>(x, Wih, bih);
    gru_rec<<<BB / 2, NTH>>>(Whh, bhh, out);
}

// round 6
// speedup vs baseline: 2.0032x; 2.0032x over previous
#include <cuda_runtime.h>
#include <cuda_bf16.h>
#include <cstdint>

#define BB 256
#define TT 2000
#define II 23
#define HH 128
#define G3 384
#define MB 8            // batches per rec CTA
#define NREC_CTAS (BB / MB)   // 32
#define HSTRIDE 136     // padded bf16 h-row stride (272B, 16B-aligned, conflict-free)
#define TCH 100
#define NCH (TT / TCH)

// bf16 gx scratch: [T][B][3H]  (~393 MB)
__device__ __nv_bfloat16 g_gx[(size_t)TT * BB * G3];

// ---- helpers ----
__device__ __forceinline__ unsigned long long fma2(unsigned long long a,
                                                   unsigned long long b,
                                                   unsigned long long c) {
    unsigned long long d;
    asm("fma.rn.f32x2 %0, %1, %2, %3;" : "=l"(d) : "l"(a), "l"(b), "l"(c));
    return d;
}
__device__ __forceinline__ unsigned long long pack2(float lo, float hi) {
    unsigned long long d;
    asm("mov.b64 %0, {%1, %2};" : "=l"(d) : "f"(lo), "f"(hi));
    return d;
}
__device__ __forceinline__ void unpack2(unsigned long long v, float& lo, float& hi) {
    asm("mov.b64 {%0, %1}, %2;" : "=f"(lo), "=f"(hi) : "l"(v));
}
__device__ __forceinline__ float tanh_ap(float x) {
    float y;
    asm("tanh.approx.f32 %0, %1;" : "=f"(y) : "f"(x));
    return y;
}
__device__ __forceinline__ float sigmoid_ap(float x) {
    return fmaf(tanh_ap(0.5f * x), 0.5f, 0.5f);
}
// pack two f32 -> bf16x2 reg (lo in bits 15:0)
__device__ __forceinline__ uint32_t pack_bf16x2(float lo, float hi) {
    uint32_t d;
    asm("cvt.rn.bf16x2.f32 %0, %1, %2;" : "=r"(d) : "f"(hi), "f"(lo));
    return d;
}
__device__ __forceinline__ float bf_lo(uint32_t v) { return __uint_as_float(v << 16); }
__device__ __forceinline__ float bf_hi(uint32_t v) { return __uint_as_float(v & 0xffff0000u); }

__device__ __forceinline__ void ldsm_x2(uint32_t& r0, uint32_t& r1, uint32_t addr) {
    asm volatile("ldmatrix.sync.aligned.m8n8.x2.shared.b16 {%0,%1}, [%2];"
                 : "=r"(r0), "=r"(r1) : "r"(addr));
}
__device__ __forceinline__ void mma_bf16(float& d0, float& d1, float& d2, float& d3,
                                         uint32_t a0, uint32_t a1, uint32_t a2, uint32_t a3,
                                         uint32_t b0, uint32_t b1,
                                         float c0, float c1, float c2, float c3) {
    asm volatile(
        "mma.sync.aligned.m16n8k16.row.col.f32.bf16.bf16.f32 "
        "{%0,%1,%2,%3},{%4,%5,%6,%7},{%8,%9},{%10,%11,%12,%13};"
        : "=f"(d0), "=f"(d1), "=f"(d2), "=f"(d3)
        : "r"(a0), "r"(a1), "r"(a2), "r"(a3), "r"(b0), "r"(b1),
          "f"(c0), "f"(c1), "f"(c2), "f"(c3));
}

// ============================================================
// Phase 1: gx[t][b][r] = W_ih[r,:].x[b,t,:] + b_ih[r]  (bf16 out)
// ============================================================
__global__ __launch_bounds__(G3) void gx_kernel(
    const float* __restrict__ x,
    const float* __restrict__ Wih,
    const float* __restrict__ bih)
{
    const int b   = blockIdx.y;
    const int t0g = blockIdx.x * TCH;
    const int r   = threadIdx.x;

    __shared__ __align__(16) float xt[II][TCH + 8];

    const float* xbase = x + ((size_t)b * TT + t0g) * II;
    for (int e = r; e < TCH * II; e += G3) {
        int t = e / II;
        int k = e - t * II;
        xt[k][t] = xbase[e];
    }

    unsigned long long ww[II];
#pragma unroll
    for (int k = 0; k < II; k++) {
        float wv = Wih[r * II + k];
        ww[k] = pack2(wv, wv);
    }
    const float bv = bih[r];
    const unsigned long long bp = pack2(bv, bv);

    __syncthreads();

    for (int t0 = 0; t0 < TCH; t0 += 4) {
        unsigned long long a01 = bp, a23 = bp;
#pragma unroll
        for (int k = 0; k < II; k++) {
            ulonglong2 xv = *reinterpret_cast<const ulonglong2*>(&xt[k][t0]);
            a01 = fma2(ww[k], xv.x, a01);
            a23 = fma2(ww[k], xv.y, a23);
        }
        float g0, g1, g2, g3;
        unpack2(a01, g0, g1);
        unpack2(a23, g2, g3);
        size_t o = ((size_t)(t0g + t0) * BB + b) * G3 + r;
        const size_t stp = (size_t)BB * G3;
        g_gx[o]           = __float2bfloat16(g0);
        g_gx[o + stp]     = __float2bfloat16(g1);
        g_gx[o + 2 * stp] = __float2bfloat16(g2);
        g_gx[o + 3 * stp] = __float2bfloat16(g3);
    }
}

// ============================================================
// Phase 2: recurrence via mma.sync bf16.
// grid 32, block 256 (8 warps). CTA handles batches [8*bx, 8*bx+8).
// Warp w owns h-col groups {2w, 2w+1} (16 h-cols) for all 3 gates.
// W_hh B-fragments register-resident. h double-buffered bf16 in smem.
// One __syncthreads per step.
// ============================================================
__global__ __launch_bounds__(256, 1) void gru_rec(
    const float* __restrict__ Whh,   // [3H, H]
    const float* __restrict__ bhh,   // [3H]
    float* __restrict__ out)         // [B, H]
{
    const int tid  = threadIdx.x;
    const int w    = tid >> 5;
    const int lane = tid & 31;
    const int g    = lane >> 2;    // 0..7  (batch row / B-frag n)
    const int tig  = lane & 3;     // 0..3  (D col pair)
    const int bg0  = blockIdx.x * MB;

    __shared__ __align__(16) __nv_bfloat16 h_sh[2][MB][HSTRIDE];

    // ---- B fragments (W_hh), loaded once: Bf[tr][gate][ks][0/1] ----
    uint32_t Bf[2][3][8][2];
#pragma unroll
    for (int tr = 0; tr < 2; tr++) {
        const int cg = 2 * w + tr;
#pragma unroll
        for (int gate = 0; gate < 3; gate++) {
            const float* Wr = Whh + (size_t)(gate * HH + cg * 8 + g) * HH;
#pragma unroll
            for (int ks = 0; ks < 8; ks++) {
                int c = ks * 16 + 2 * tig;
                float2 v0 = *reinterpret_cast<const float2*>(Wr + c);
                float2 v1 = *reinterpret_cast<const float2*>(Wr + c + 8);
                Bf[tr][gate][ks][0] = pack_bf16x2(v0.x, v0.y);
                Bf[tr][gate][ks][1] = pack_bf16x2(v1.x, v1.y);
            }
        }
    }

    // ---- biases (b_hh) for this lane's columns ----
    float bias[2][3][2];
#pragma unroll
    for (int tr = 0; tr < 2; tr++) {
        const int col = (2 * w + tr) * 8 + 2 * tig;
#pragma unroll
        for (int gate = 0; gate < 3; gate++) {
            bias[tr][gate][0] = bhh[gate * HH + col];
            bias[tr][gate][1] = bhh[gate * HH + col + 1];
        }
    }

    // zero both h buffers
    for (int i = tid; i < 2 * MB * HSTRIDE; i += 256)
        reinterpret_cast<__nv_bfloat16*>(h_sh)[i] = __float2bfloat16(0.0f);

    // ---- gx byte offsets (bf16 array; total < 4GB so u32 math ok) ----
    const uint32_t gx_step = (uint32_t)(BB * G3 * 2);
    uint32_t gxoff[2][3];
#pragma unroll
    for (int tr = 0; tr < 2; tr++) {
        const int col = (2 * w + tr) * 8 + 2 * tig;
#pragma unroll
        for (int gate = 0; gate < 3; gate++)
            gxoff[tr][gate] = (uint32_t)(((bg0 + g) * G3 + gate * HH + col) * 2);
    }
    const char* gxb = reinterpret_cast<const char*>(g_gx);

    uint32_t gcur[2][3];
#pragma unroll
    for (int tr = 0; tr < 2; tr++)
#pragma unroll
        for (int gate = 0; gate < 3; gate++)
            gcur[tr][gate] = *reinterpret_cast<const uint32_t*>(gxb + gxoff[tr][gate]);

    float hp[2][2]   = {{0.f, 0.f}, {0.f, 0.f}};   // h_old (f32) for own cols
    float hsum[2][2] = {{0.f, 0.f}, {0.f, 0.f}};

    // ldmatrix source address (lanes 0..15 meaningful)
    const int arow  = lane & 7;
    const int ahalf = (lane >> 3) & 1;
    uint32_t hbase[2];
    hbase[0] = (uint32_t)__cvta_generic_to_shared(&h_sh[0][0][0]) +
               arow * (HSTRIDE * 2) + ahalf * 16;
    hbase[1] = (uint32_t)__cvta_generic_to_shared(&h_sh[1][0][0]) +
               arow * (HSTRIDE * 2) + ahalf * 16;

    __syncthreads();

    int cur = 0;
    for (int t = 0; t < TT; t++) {
        // prefetch next step's gx
        uint32_t gnxt[2][3];
        if (t + 1 < TT) {
            const char* p = gxb + (size_t)(t + 1) * gx_step;
#pragma unroll
            for (int tr = 0; tr < 2; tr++)
#pragma unroll
                for (int gate = 0; gate < 3; gate++)
                    gnxt[tr][gate] = *reinterpret_cast<const uint32_t*>(p + gxoff[tr][gate]);
        } else {
#pragma unroll
            for (int tr = 0; tr < 2; tr++)
#pragma unroll
                for (int gate = 0; gate < 3; gate++) gnxt[tr][gate] = 0;
        }

        // load A fragments (h, bf16) for all 8 k-steps
        uint32_t A0[8], A2[8];
#pragma unroll
        for (int ks = 0; ks < 8; ks++)
            ldsm_x2(A0[ks], A2[ks], hbase[cur] + ks * 32);

        // MMA: D[tr][gate] (only c0,c1 real; rows 8..15 are zero-padding)
        float D[2][3][4];
#pragma unroll
        for (int tr = 0; tr < 2; tr++)
#pragma unroll
            for (int gate = 0; gate < 3; gate++) {
                float d0 = 0.f, d1 = 0.f, d2 = 0.f, d3 = 0.f;
#pragma unroll
                for (int ks = 0; ks < 8; ks++)
                    mma_bf16(d0, d1, d2, d3,
                             A0[ks], 0u, A2[ks], 0u,
                             Bf[tr][gate][ks][0], Bf[tr][gate][ks][1],
                             d0, d1, d2, d3);
                D[tr][gate][0] = d0; D[tr][gate][1] = d1;
                D[tr][gate][2] = d2; D[tr][gate][3] = d3;
            }

        // epilogue: gates + h update, all in registers
#pragma unroll
        for (int tr = 0; tr < 2; tr++) {
            float gxr0 = bf_lo(gcur[tr][0]), gxr1 = bf_hi(gcur[tr][0]);
            float gxz0 = bf_lo(gcur[tr][1]), gxz1 = bf_hi(gcur[tr][1]);
            float gxn0 = bf_lo(gcur[tr][2]), gxn1 = bf_hi(gcur[tr][2]);

            float rr0 = sigmoid_ap(D[tr][0][0] + bias[tr][0][0] + gxr0);
            float rr1 = sigmoid_ap(D[tr][0][1] + bias[tr][0][1] + gxr1);
            float zz0 = sigmoid_ap(D[tr][1][0] + bias[tr][1][0] + gxz0);
            float zz1 = sigmoid_ap(D[tr][1][1] + bias[tr][1][1] + gxz1);
            float nn0 = tanh_ap(fmaf(rr0, D[tr][2][0] + bias[tr][2][0], gxn0));
            float nn1 = tanh_ap(fmaf(rr1, D[tr][2][1] + bias[tr][2][1], gxn1));

            float h0 = fmaf(zz0, hp[tr][0] - nn0, nn0);
            float h1 = fmaf(zz1, hp[tr][1] - nn1, nn1);
            hp[tr][0] = h0;  hp[tr][1] = h1;
            hsum[tr][0] += h0;  hsum[tr][1] += h1;

            const int col = (2 * w + tr) * 8 + 2 * tig;
            *reinterpret_cast<uint32_t*>(&h_sh[cur ^ 1][g][col]) = pack_bf16x2(h0, h1);
        }

        __syncthreads();
        cur ^= 1;
#pragma unroll
        for (int tr = 0; tr < 2; tr++)
#pragma unroll
            for (int gate = 0; gate < 3; gate++) gcur[tr][gate] = gnxt[tr][gate];
    }

#pragma unroll
    for (int tr = 0; tr < 2; tr++) {
        const int col = (2 * w + tr) * 8 + 2 * tig;
        out[(bg0 + g) * HH + col]     = hsum[tr][0] * (1.0f / (float)TT);
        out[(bg0 + g) * HH + col + 1] = hsum[tr][1] * (1.0f / (float)TT);
    }
}

extern "C" void kernel_launch(void* const* d_in, const int* in_sizes, int n_in,
                              void* d_out, int out_size) {
    const float* x   = (const float*)d_in[0];
    const float* Wih = (const float*)d_in[1];
    const float* Whh = (const float*)d_in[2];
    const float* bih = (const float*)d_in[3];
    const float* bhh = (const float*)d_in[4];
    float* out = (float*)d_out;
    (void)in_sizes; (void)n_in; (void)out_size;

    gx_kernel<<<dim3(NCH, BB), G3>>>(x, Wih, bih);
    gru_rec<<<NREC_CTAS, 256>>>(Whh, bhh, out);
}

// round 7
// speedup vs baseline: 2.6033x; 1.2996x over previous
#include <cuda_runtime.h>
#include <cuda_fp16.h>
#include <cstdint>

#define BB 256
#define TT 2000
#define II 23
#define HH 128
#define G3 384
#define MB 8                   // batches per rec CTA
#define NREC_CTAS (BB / MB)    // 32
#define WPB 8                  // warps per rec CTA
#define HSTRIDE 136            // padded fp16 h-row stride (272B)
#define TCH 100
#define NCH (TT / TCH)

// gx scratch in FRAGMENT layout, fp16x2 words:
// byte offset(t, cta, warp, p, lane, wi) =
//   t*196608 + cta*6144 + warp*768 + p*256 + lane*8 + wi*4
// word w6 = tr*3 + gate  ->  p = w6>>1, wi = w6&1 ; halves = (col, col+1)
#define GX_TSTEP 196608u
__device__ uint32_t g_gx2[(size_t)TT * NREC_CTAS * WPB * 192];

// ---- helpers ----
__device__ __forceinline__ unsigned long long fma2(unsigned long long a,
                                                   unsigned long long b,
                                                   unsigned long long c) {
    unsigned long long d;
    asm("fma.rn.f32x2 %0, %1, %2, %3;" : "=l"(d) : "l"(a), "l"(b), "l"(c));
    return d;
}
__device__ __forceinline__ unsigned long long pack2(float lo, float hi) {
    unsigned long long d;
    asm("mov.b64 %0, {%1, %2};" : "=l"(d) : "f"(lo), "f"(hi));
    return d;
}
__device__ __forceinline__ void unpack2(unsigned long long v, float& lo, float& hi) {
    asm("mov.b64 {%0, %1}, %2;" : "=f"(lo), "=f"(hi) : "l"(v));
}
__device__ __forceinline__ float tanh_ap(float x) {
    float y;
    asm("tanh.approx.f32 %0, %1;" : "=f"(y) : "f"(x));
    return y;
}
__device__ __forceinline__ float sigmoid_ap(float x) {
    return fmaf(tanh_ap(0.5f * x), 0.5f, 0.5f);
}
// pack two f32 -> f16x2 (lo in bits 15:0)
__device__ __forceinline__ uint32_t pack_h2(float lo, float hi) {
    uint32_t d;
    asm("cvt.rn.f16x2.f32 %0, %1, %2;" : "=r"(d) : "f"(hi), "f"(lo));
    return d;
}
__device__ __forceinline__ float h2_lo(uint32_t v) {
    return __half2float(__low2half(*reinterpret_cast<const __half2*>(&v)));
}
__device__ __forceinline__ float h2_hi(uint32_t v) {
    return __half2float(__high2half(*reinterpret_cast<const __half2*>(&v)));
}

__device__ __forceinline__ void ldsm_x2(uint32_t& r0, uint32_t& r1, uint32_t addr) {
    asm volatile("ldmatrix.sync.aligned.m8n8.x2.shared.b16 {%0,%1}, [%2];"
                 : "=r"(r0), "=r"(r1) : "r"(addr));
}
__device__ __forceinline__ void mma_f16(float& d0, float& d1, float& d2, float& d3,
                                        uint32_t a0, uint32_t a1, uint32_t a2, uint32_t a3,
                                        uint32_t b0, uint32_t b1,
                                        float c0, float c1, float c2, float c3) {
    asm volatile(
        "mma.sync.aligned.m16n8k16.row.col.f32.f16.f16.f32 "
        "{%0,%1,%2,%3},{%4,%5,%6,%7},{%8,%9},{%10,%11,%12,%13};"
        : "=f"(d0), "=f"(d1), "=f"(d2), "=f"(d3)
        : "r"(a0), "r"(a1), "r"(a2), "r"(a3), "r"(b0), "r"(b1),
          "f"(c0), "f"(c1), "f"(c2), "f"(c3));
}

// ============================================================
// Phase 1: gx = W_ih.x + b_ih, written in rec-fragment layout (f16x2).
// grid (NCH, BB), block 384; thread r owns gate-row r.
// ============================================================
__global__ __launch_bounds__(G3) void gx_kernel(
    const float* __restrict__ x,
    const float* __restrict__ Wih,
    const float* __restrict__ bih)
{
    const int b   = blockIdx.y;
    const int t0g = blockIdx.x * TCH;
    const int r   = threadIdx.x;

    __shared__ __align__(16) float xt[II][TCH + 8];

    const float* xbase = x + ((size_t)b * TT + t0g) * II;
    for (int e = r; e < TCH * II; e += G3) {
        int t = e / II;
        int k = e - t * II;
        xt[k][t] = xbase[e];
    }

    unsigned long long ww[II];
#pragma unroll
    for (int k = 0; k < II; k++) {
        float wv = Wih[r * II + k];
        ww[k] = pack2(wv, wv);
    }
    const float bv = bih[r];
    const unsigned long long bp = pack2(bv, bv);

    // fragment-layout address components for this row r and batch b
    const int gate = r >> 7;
    const int col  = r & 127;
    const int wp   = col >> 4;
    const int tr   = (col >> 3) & 1;
    const int tig  = (col & 7) >> 1;
    const int w6   = tr * 3 + gate;
    const int cta  = b >> 3;
    const int g    = b & 7;
    const int lane2 = g * 4 + tig;
    // byte offset within a t-block:
    const uint32_t inoff = (uint32_t)(cta * 6144 + wp * 768 + (w6 >> 1) * 256 +
                                      lane2 * 8 + (w6 & 1) * 4);
    char* gxb = reinterpret_cast<char*>(g_gx2);
    const bool writer = ((r & 1) == 0);

    __syncthreads();

    for (int t0 = 0; t0 < TCH; t0 += 4) {
        unsigned long long a01 = bp, a23 = bp;
#pragma unroll
        for (int k = 0; k < II; k++) {
            ulonglong2 xv = *reinterpret_cast<const ulonglong2*>(&xt[k][t0]);
            a01 = fma2(ww[k], xv.x, a01);
            a23 = fma2(ww[k], xv.y, a23);
        }
        float g0, g1, g2, g3;
        unpack2(a01, g0, g1);
        unpack2(a23, g2, g3);

        // pair with row col+1 (next lane) and write f16x2
        float q0 = __shfl_down_sync(0xffffffffu, g0, 1);
        float q1 = __shfl_down_sync(0xffffffffu, g1, 1);
        float q2 = __shfl_down_sync(0xffffffffu, g2, 1);
        float q3 = __shfl_down_sync(0xffffffffu, g3, 1);
        if (writer) {
            uint32_t base = (uint32_t)(t0g + t0) * GX_TSTEP + inoff;
            *reinterpret_cast<uint32_t*>(gxb + base)                = pack_h2(g0, q0);
            *reinterpret_cast<uint32_t*>(gxb + base + GX_TSTEP)     = pack_h2(g1, q1);
            *reinterpret_cast<uint32_t*>(gxb + base + 2 * GX_TSTEP) = pack_h2(g2, q2);
            *reinterpret_cast<uint32_t*>(gxb + base + 3 * GX_TSTEP) = pack_h2(g3, q3);
        }
    }
}

// ============================================================
// Phase 2: recurrence via mma.sync fp16 (f32 accum).
// grid 32, block 256 (8 warps). Warp w owns h-col groups {2w,2w+1}
// for all 3 gates. W_hh frags register-resident, h double-buffered
// fp16 smem, 1 barrier/step, gx loaded as 3 coalesced LDG.64.
// ============================================================
__global__ __launch_bounds__(256, 1) void gru_rec(
    const float* __restrict__ Whh,   // [3H, H]
    const float* __restrict__ bhh,   // [3H]
    float* __restrict__ out)         // [B, H]
{
    const int tid  = threadIdx.x;
    const int w    = tid >> 5;
    const int lane = tid & 31;
    const int g    = lane >> 2;
    const int tig  = lane & 3;
    const int bg0  = blockIdx.x * MB;

    __shared__ __align__(16) __half h_sh[2][MB][HSTRIDE];

    // B fragments (W_hh) fp16, loaded once
    uint32_t Bf[2][3][8][2];
#pragma unroll
    for (int tr = 0; tr < 2; tr++) {
        const int cg = 2 * w + tr;
#pragma unroll
        for (int gate = 0; gate < 3; gate++) {
            const float* Wr = Whh + (size_t)(gate * HH + cg * 8 + g) * HH;
#pragma unroll
            for (int ks = 0; ks < 8; ks++) {
                int c = ks * 16 + 2 * tig;
                float2 v0 = *reinterpret_cast<const float2*>(Wr + c);
                float2 v1 = *reinterpret_cast<const float2*>(Wr + c + 8);
                Bf[tr][gate][ks][0] = pack_h2(v0.x, v0.y);
                Bf[tr][gate][ks][1] = pack_h2(v1.x, v1.y);
            }
        }
    }

    float bias[2][3][2];
#pragma unroll
    for (int tr = 0; tr < 2; tr++) {
        const int col = (2 * w + tr) * 8 + 2 * tig;
#pragma unroll
        for (int gate = 0; gate < 3; gate++) {
            bias[tr][gate][0] = bhh[gate * HH + col];
            bias[tr][gate][1] = bhh[gate * HH + col + 1];
        }
    }

    for (int i = tid; i < 2 * MB * HSTRIDE; i += 256)
        reinterpret_cast<__half*>(h_sh)[i] = __float2half(0.0f);

    // coalesced gx base: this thread reads 3 x u64 per step
    const char* gxb = reinterpret_cast<const char*>(g_gx2);
    const uint32_t myoff = (uint32_t)(blockIdx.x * 6144 + w * 768 + lane * 8);

    uint2 gcur[3];
#pragma unroll
    for (int p = 0; p < 3; p++)
        gcur[p] = *reinterpret_cast<const uint2*>(gxb + myoff + p * 256);

    float hp[2][2]   = {{0.f, 0.f}, {0.f, 0.f}};
    float hsum[2][2] = {{0.f, 0.f}, {0.f, 0.f}};

    const int arow  = lane & 7;
    const int ahalf = (lane >> 3) & 1;
    uint32_t hbase[2];
    hbase[0] = (uint32_t)__cvta_generic_to_shared(&h_sh[0][0][0]) +
               arow * (HSTRIDE * 2) + ahalf * 16;
    hbase[1] = (uint32_t)__cvta_generic_to_shared(&h_sh[1][0][0]) +
               arow * (HSTRIDE * 2) + ahalf * 16;

    __syncthreads();

    int cur = 0;
    for (int t = 0; t < TT; t++) {
        // prefetch next step's gx (3 coalesced LDG.64)
        uint2 gnxt[3];
        if (t + 1 < TT) {
            const char* p = gxb + (size_t)(t + 1) * GX_TSTEP + myoff;
            gnxt[0] = *reinterpret_cast<const uint2*>(p);
            gnxt[1] = *reinterpret_cast<const uint2*>(p + 256);
            gnxt[2] = *reinterpret_cast<const uint2*>(p + 512);
        } else {
            gnxt[0] = gnxt[1] = gnxt[2] = make_uint2(0u, 0u);
        }

        uint32_t A0[8], A2[8];
#pragma unroll
        for (int ks = 0; ks < 8; ks++)
            ldsm_x2(A0[ks], A2[ks], hbase[cur] + ks * 32);

        float D[2][3][4];
#pragma unroll
        for (int tr = 0; tr < 2; tr++)
#pragma unroll
            for (int gate = 0; gate < 3; gate++) {
                float d0 = 0.f, d1 = 0.f, d2 = 0.f, d3 = 0.f;
#pragma unroll
                for (int ks = 0; ks < 8; ks++)
                    mma_f16(d0, d1, d2, d3,
                            A0[ks], 0u, A2[ks], 0u,
                            Bf[tr][gate][ks][0], Bf[tr][gate][ks][1],
                            d0, d1, d2, d3);
                D[tr][gate][0] = d0; D[tr][gate][1] = d1;
                D[tr][gate][2] = d2; D[tr][gate][3] = d3;
            }

        // epilogue (all in registers). word w6 = tr*3+gate -> gcur[w6>>1].x/.y
#pragma unroll
        for (int tr = 0; tr < 2; tr++) {
            uint32_t wr = (tr == 0) ? gcur[0].x : gcur[1].y;   // w6 = 0 / 3
            uint32_t wz = (tr == 0) ? gcur[0].y : gcur[2].x;   // w6 = 1 / 4
            uint32_t wn = (tr == 0) ? gcur[1].x : gcur[2].y;   // w6 = 2 / 5

            float rr0 = sigmoid_ap(D[tr][0][0] + bias[tr][0][0] + h2_lo(wr));
            float rr1 = sigmoid_ap(D[tr][0][1] + bias[tr][0][1] + h2_hi(wr));
            float zz0 = sigmoid_ap(D[tr][1][0] + bias[tr][1][0] + h2_lo(wz));
            float zz1 = sigmoid_ap(D[tr][1][1] + bias[tr][1][1] + h2_hi(wz));
            float nn0 = tanh_ap(fmaf(rr0, D[tr][2][0] + bias[tr][2][0], h2_lo(wn)));
            float nn1 = tanh_ap(fmaf(rr1, D[tr][2][1] + bias[tr][2][1], h2_hi(wn)));

            float h0 = fmaf(zz0, hp[tr][0] - nn0, nn0);
            float h1 = fmaf(zz1, hp[tr][1] - nn1, nn1);
            hp[tr][0] = h0;  hp[tr][1] = h1;
            hsum[tr][0] += h0;  hsum[tr][1] += h1;

            const int col = (2 * w + tr) * 8 + 2 * tig;
            *reinterpret_cast<uint32_t*>(&h_sh[cur ^ 1][g][col]) = pack_h2(h0, h1);
        }

        __syncthreads();
        cur ^= 1;
        gcur[0] = gnxt[0];  gcur[1] = gnxt[1];  gcur[2] = gnxt[2];
    }

#pragma unroll
    for (int tr = 0; tr < 2; tr++) {
        const int col = (2 * w + tr) * 8 + 2 * tig;
        out[(bg0 + g) * HH + col]     = hsum[tr][0] * (1.0f / (float)TT);
        out[(bg0 + g) * HH + col + 1] = hsum[tr][1] * (1.0f / (float)TT);
    }
}

extern "C" void kernel_launch(void* const* d_in, const int* in_sizes, int n_in,
                              void* d_out, int out_size) {
    const float* x   = (const float*)d_in[0];
    const float* Wih = (const float*)d_in[1];
    const float* Whh = (const float*)d_in[2];
    const float* bih = (const float*)d_in[3];
    const float* bhh = (const float*)d_in[4];
    float* out = (float*)d_out;
    (void)in_sizes; (void)n_in; (void)out_size;

    gx_kernel<<<dim3(NCH, BB), G3>>>(x, Wih, bih);
    gru_rec<<<NREC_CTAS, 256>>>(Whh, bhh, out);
}